// round 1
// baseline (speedup 1.0000x reference)
#include <cuda_runtime.h>

// ---------------- Problem constants ----------------
#define NMAX    50000
#define EMAX    800000
#define ETOTMAX (EMAX + NMAX)
#define GG      64
#define INC     128
#define HIDC    64
#define NHEADS  4
#define F1      (NHEADS * HIDC)   // 256
#define OUTC    10
#define NEG     0.2f
#define EPSV    1e-16f

// ---------------- Device scratch (no cudaMalloc allowed) ----------------
__device__ float    d_h[(size_t)NMAX * F1];       // post-GEMM features of current layer
__device__ float    d_feat[(size_t)NMAX * F1];    // aggregated layer output (= next layer input)
__device__ float    d_asrc[NMAX * NHEADS];
__device__ float    d_adst[NMAX * NHEADS];
__device__ unsigned d_segmax[NMAX * NHEADS];
__device__ float    d_segsum[NMAX * NHEADS];
__device__ float    d_alpha[(size_t)ETOTMAX * NHEADS];
__device__ float    d_pool[GG * HIDC];
__device__ float    d_cnt[GG];

// Monotonic float<->uint encoding so atomicMax(unsigned) == float max
__device__ __forceinline__ unsigned fenc(float f) {
    unsigned u = __float_as_uint(f);
    return (u & 0x80000000u) ? ~u : (u | 0x80000000u);
}
__device__ __forceinline__ float fdec(unsigned u) {
    u = (u & 0x80000000u) ? (u & 0x7FFFFFFFu) : ~u;
    return __uint_as_float(u);
}

// ---------------- GEMM: C(d_h)[M,NOUT] = A[M,K] @ B[K,NOUT] ----------------
// AG=true -> A is the internal d_feat buffer; else the external input pointer.
template <int K, int NOUT, bool AG>
__global__ void sgemm_k(const float* __restrict__ Ain, const float* __restrict__ B, int M) {
    constexpr int BM = 64, BN = 64, BK = 16;
    __shared__ float As[BK][BM];
    __shared__ float Bs[BK][BN];
    const float* A = AG ? (const float*)d_feat : Ain;

    int tid = threadIdx.x;           // 256 threads
    int tx = tid & 15, ty = tid >> 4;
    int row0 = blockIdx.y * BM;
    int col0 = blockIdx.x * BN;
    float acc[4][4] = {};

    for (int k0 = 0; k0 < K; k0 += BK) {
#pragma unroll
        for (int i = tid; i < BM * BK; i += 256) {
            int m = i >> 4, k = i & 15;
            int gr = row0 + m;
            As[k][m] = (gr < M) ? A[(size_t)gr * K + k0 + k] : 0.f;
        }
#pragma unroll
        for (int i = tid; i < BK * BN; i += 256) {
            int k = i >> 6, nn = i & 63;
            Bs[k][nn] = B[(size_t)(k0 + k) * NOUT + col0 + nn];
        }
        __syncthreads();
#pragma unroll
        for (int k = 0; k < BK; k++) {
            float a[4], b[4];
#pragma unroll
            for (int i = 0; i < 4; i++) a[i] = As[k][ty * 4 + i];
#pragma unroll
            for (int j = 0; j < 4; j++) b[j] = Bs[k][tx * 4 + j];
#pragma unroll
            for (int i = 0; i < 4; i++)
#pragma unroll
                for (int j = 0; j < 4; j++) acc[i][j] = fmaf(a[i], b[j], acc[i][j]);
        }
        __syncthreads();
    }
#pragma unroll
    for (int i = 0; i < 4; i++) {
        int gr = row0 + ty * 4 + i;
        if (gr < M) {
#pragma unroll
            for (int j = 0; j < 4; j++)
                d_h[(size_t)gr * NOUT + col0 + tx * 4 + j] = acc[i][j];
        }
    }
}

// ---------------- attention coefficients: asrc/adst[n,H] = <h[n,h,:], a_*[h,:]> ----------------
template <int H, int C>
__global__ void attn_coef(const float* __restrict__ a_src, const float* __restrict__ a_dst, int n) {
    int gw = (blockIdx.x * blockDim.x + threadIdx.x) >> 5;
    int lane = threadIdx.x & 31;
    if (gw >= n * H) return;
    int node = gw / H, hd = gw % H;
    const float* hr = d_h + (size_t)node * H * C + hd * C;
    float s1 = 0.f, s2 = 0.f;
#pragma unroll
    for (int c = lane; c < C; c += 32) {
        float v = hr[c];
        s1 += v * a_src[hd * C + c];
        s2 += v * a_dst[hd * C + c];
    }
#pragma unroll
    for (int o = 16; o; o >>= 1) {
        s1 += __shfl_xor_sync(0xffffffffu, s1, o);
        s2 += __shfl_xor_sync(0xffffffffu, s2, o);
    }
    if (!lane) { d_asrc[gw] = s1; d_adst[gw] = s2; }
}

// ---------------- per-layer init: out = bias broadcast; segmax=-inf; segsum=0 ----------------
template <int H, int F>
__global__ void init_layer(const float* __restrict__ bias, int n) {
    int i = blockIdx.x * blockDim.x + threadIdx.x;
    if (i < n * F) d_feat[i] = bias[i % F];
    if (i < n * H) { d_segmax[i] = fenc(-3.402823466e38f); d_segsum[i] = 0.f; }
}

// ---------------- edge pass A: segment max of leaky_relu(asrc[s]+adst[d]) ----------------
template <int H>
__global__ void edge_max(const int* __restrict__ ei, int E, int n) {
    int e = blockIdx.x * blockDim.x + threadIdx.x;
    int Etot = E + n;
    if (e >= Etot) return;
    int s, d;
    if (e < E) { s = __ldg(&ei[e]); d = __ldg(&ei[E + e]); } else { s = d = e - E; }
#pragma unroll
    for (int h = 0; h < H; h++) {
        float v = d_asrc[s * H + h] + d_adst[d * H + h];
        v = v > 0.f ? v : NEG * v;
        atomicMax(&d_segmax[d * H + h], fenc(v));
    }
}

// ---------------- edge pass B: alpha=exp(e-m), segment sum ----------------
template <int H>
__global__ void edge_exp(const int* __restrict__ ei, int E, int n) {
    int e = blockIdx.x * blockDim.x + threadIdx.x;
    int Etot = E + n;
    if (e >= Etot) return;
    int s, d;
    if (e < E) { s = __ldg(&ei[e]); d = __ldg(&ei[E + e]); } else { s = d = e - E; }
#pragma unroll
    for (int h = 0; h < H; h++) {
        float v = d_asrc[s * H + h] + d_adst[d * H + h];
        v = v > 0.f ? v : NEG * v;
        float m = fdec(d_segmax[d * H + h]);
        float ex = __expf(v - m);
        d_alpha[(size_t)e * H + h] = ex;
        atomicAdd(&d_segsum[d * H + h], ex);
    }
}

// ---------------- edge pass C: out[dst] += h[src] * alpha/denom (warp per edge) ----------------
template <int H, int C>
__global__ void edge_msg(const int* __restrict__ ei, int E, int n) {
    constexpr int F = H * C;
    int warp = (blockIdx.x * blockDim.x + threadIdx.x) >> 5;
    int lane = threadIdx.x & 31;
    int Etot = E + n;
    if (warp >= Etot) return;
    int s, d;
    if (warp < E) { s = __ldg(&ei[warp]); d = __ldg(&ei[E + warp]); } else { s = d = warp - E; }
    float w[H];
#pragma unroll
    for (int h = 0; h < H; h++)
        w[h] = d_alpha[(size_t)warp * H + h] / (d_segsum[(size_t)d * H + h] + EPSV);
    const float4* hsrc = reinterpret_cast<const float4*>(&d_h[(size_t)s * F]);
    float* outd = &d_feat[(size_t)d * F];
#pragma unroll
    for (int i = lane; i < F / 4; i += 32) {
        float4 v = hsrc[i];
        float wh = w[(i * 4) / C];
        atomicAdd(&outd[i * 4 + 0], v.x * wh);
        atomicAdd(&outd[i * 4 + 1], v.y * wh);
        atomicAdd(&outd[i * 4 + 2], v.z * wh);
        atomicAdd(&outd[i * 4 + 3], v.w * wh);
    }
}

// ---------------- ELU in place on d_feat ----------------
__global__ void elu_k(int tot) {
    int i = blockIdx.x * blockDim.x + threadIdx.x;
    if (i >= tot) return;
    float v = d_feat[i];
    d_feat[i] = v > 0.f ? v : (__expf(v) - 1.f);
}

// ---------------- pooling + head ----------------
__global__ void pool_zero() {
    for (int i = threadIdx.x; i < GG * HIDC; i += blockDim.x) d_pool[i] = 0.f;
    if (threadIdx.x < GG) d_cnt[threadIdx.x] = 0.f;
}

__global__ void pool_add(const int* __restrict__ batch, int n) {
    int i = blockIdx.x * blockDim.x + threadIdx.x;
    if (i >= n * HIDC) return;
    int node = i / HIDC, c = i % HIDC;
    int g = __ldg(&batch[node]);
    atomicAdd(&d_pool[g * HIDC + c], d_feat[(size_t)node * HIDC + c]);
    if (c == 0) atomicAdd(&d_cnt[g], 1.0f);
}

__global__ void head_k(const float* __restrict__ Wc, const float* __restrict__ bc,
                       float* __restrict__ out) {
    int t = blockIdx.x * blockDim.x + threadIdx.x;
    if (t >= GG * OUTC) return;
    int g = t / OUTC, o = t % OUTC;
    float inv = 1.f / fmaxf(d_cnt[g], 1.f);
    float s = 0.f;
#pragma unroll
    for (int c = 0; c < HIDC; c++) s += d_pool[g * HIDC + c] * Wc[c * OUTC + o];
    out[t] = s * inv + bc[o];
}

// ---------------- host orchestration ----------------
extern "C" void kernel_launch(void* const* d_in, const int* in_sizes, int n_in,
                              void* d_out, int out_size) {
    const float* x   = (const float*)d_in[0];
    const int*   ei  = (const int*)d_in[1];
    const int*   bat = (const int*)d_in[2];
    const float* W1 = (const float*)d_in[3],  *as1 = (const float*)d_in[4],
               * ad1 = (const float*)d_in[5], *b1  = (const float*)d_in[6];
    const float* W2 = (const float*)d_in[7],  *as2 = (const float*)d_in[8],
               * ad2 = (const float*)d_in[9], *b2  = (const float*)d_in[10];
    const float* W3 = (const float*)d_in[11], *as3 = (const float*)d_in[12],
               * ad3 = (const float*)d_in[13],*b3  = (const float*)d_in[14];
    const float* Wc = (const float*)d_in[15], *bc  = (const float*)d_in[16];
    float* out = (float*)d_out;

    int n    = in_sizes[0] / INC;
    int E    = in_sizes[1] / 2;
    int Etot = E + n;

    int gemm_rows = (n + 63) / 64;
    int eb  = (Etot + 255) / 256;                 // thread-per-edge kernels
    int ebw = (int)(((long long)Etot * 32 + 255) / 256);  // warp-per-edge kernel
    int nhb4 = (n * NHEADS * 32 + 255) / 256;
    int nfb  = (n * F1 + 255) / 256;

    // ---- Layer 1 (heads=4, in=128, out=256) ----
    sgemm_k<INC, F1, false><<<dim3(F1 / 64, gemm_rows), 256>>>(x, W1, n);
    attn_coef<NHEADS, HIDC><<<nhb4, 256>>>(as1, ad1, n);
    init_layer<NHEADS, F1><<<nfb, 256>>>(b1, n);
    edge_max<NHEADS><<<eb, 256>>>(ei, E, n);
    edge_exp<NHEADS><<<eb, 256>>>(ei, E, n);
    edge_msg<NHEADS, HIDC><<<ebw, 256>>>(ei, E, n);
    elu_k<<<nfb, 256>>>(n * F1);

    // ---- Layer 2 (heads=4, in=256, out=256) ----
    sgemm_k<F1, F1, true><<<dim3(F1 / 64, gemm_rows), 256>>>(nullptr, W2, n);
    attn_coef<NHEADS, HIDC><<<nhb4, 256>>>(as2, ad2, n);
    init_layer<NHEADS, F1><<<nfb, 256>>>(b2, n);
    edge_max<NHEADS><<<eb, 256>>>(ei, E, n);
    edge_exp<NHEADS><<<eb, 256>>>(ei, E, n);
    edge_msg<NHEADS, HIDC><<<ebw, 256>>>(ei, E, n);
    elu_k<<<nfb, 256>>>(n * F1);

    // ---- Layer 3 (heads=1, in=256, out=64) ----
    sgemm_k<F1, HIDC, true><<<dim3(1, gemm_rows), 256>>>(nullptr, W3, n);
    attn_coef<1, HIDC><<<(n * 32 + 255) / 256, 256>>>(as3, ad3, n);
    init_layer<1, HIDC><<<(n * HIDC + 255) / 256, 256>>>(b3, n);
    edge_max<1><<<eb, 256>>>(ei, E, n);
    edge_exp<1><<<eb, 256>>>(ei, E, n);
    edge_msg<1, HIDC><<<ebw, 256>>>(ei, E, n);

    // ---- Global mean pool + linear head ----
    pool_zero<<<1, 256>>>();
    pool_add<<<(n * HIDC + 255) / 256, 256>>>(bat, n);
    head_k<<<(GG * OUTC + 255) / 256, 256>>>(Wc, bc, out);
}

// round 2
// speedup vs baseline: 2.7308x; 2.7308x over previous
#include <cuda_runtime.h>

// ---------------- Problem constants ----------------
#define NMAX    50000
#define EMAX    800000
#define ETOTMAX (EMAX + NMAX)
#define GG      64
#define INC     128
#define HIDC    64
#define NHEADS  4
#define F1      (NHEADS * HIDC)   // 256
#define OUTC    10
#define NEG     0.2f
#define EPSV    1e-16f

// ---------------- Device scratch (no cudaMalloc allowed) ----------------
__device__ float d_h[(size_t)NMAX * F1];      // post-GEMM features of current layer
__device__ float d_feat[(size_t)NMAX * F1];   // aggregated layer output (= next layer input)
__device__ float d_asrc[NMAX * NHEADS];
__device__ float d_adst[NMAX * NHEADS];
__device__ int   d_deg[NMAX];
__device__ int   d_off[NMAX];
__device__ int   d_cur[NMAX];
__device__ int   d_csr_src[ETOTMAX];
__device__ float d_pool[GG * HIDC];
__device__ float d_cnt[GG];

// ================= CSR construction =================
__global__ void zero_deg(int n) {
    int i = blockIdx.x * blockDim.x + threadIdx.x;
    if (i < n) { d_deg[i] = 0; d_cur[i] = 0; }
}

__global__ void hist_k(const int* __restrict__ ei, int E, int n) {
    int e = blockIdx.x * blockDim.x + threadIdx.x;
    int Etot = E + n;
    if (e >= Etot) return;
    int d = (e < E) ? __ldg(&ei[E + e]) : (e - E);
    atomicAdd(&d_deg[d], 1);
}

// single-block exclusive scan of d_deg -> d_off
__global__ void scan_k(int n) {
    const int T = 1024;
    int tid = threadIdx.x;
    int chunk = (n + T - 1) / T;
    int b = tid * chunk;
    int e = min(b + chunk, n);
    int s = 0;
    for (int i = b; i < e; i++) s += d_deg[i];
    __shared__ int ws[32];
    int lane = tid & 31, wid = tid >> 5;
    int v = s;
#pragma unroll
    for (int o = 1; o < 32; o <<= 1) {
        int t = __shfl_up_sync(0xffffffffu, v, o);
        if (lane >= o) v += t;
    }
    if (lane == 31) ws[wid] = v;
    __syncthreads();
    if (wid == 0) {
        int w = (tid < 32) ? ws[tid] : 0;
#pragma unroll
        for (int o = 1; o < 32; o <<= 1) {
            int t = __shfl_up_sync(0xffffffffu, w, o);
            if (lane >= o) w += t;
        }
        if (tid < 32) ws[tid] = w;
    }
    __syncthreads();
    int excl = v - s + (wid ? ws[wid - 1] : 0);
    for (int i = b; i < e; i++) { d_off[i] = excl; excl += d_deg[i]; }
}

__global__ void scatter_k(const int* __restrict__ ei, int E, int n) {
    int e = blockIdx.x * blockDim.x + threadIdx.x;
    int Etot = E + n;
    if (e >= Etot) return;
    int s, d;
    if (e < E) { s = __ldg(&ei[e]); d = __ldg(&ei[E + e]); } else { s = d = e - E; }
    int pos = d_off[d] + atomicAdd(&d_cur[d], 1);
    d_csr_src[pos] = s;
}

// ================= GEMM: d_h[M,NOUT] = A[M,K] @ B[K,NOUT] =================
// BM=128, BK=8, TM=8; BN/TN templated (128/8 or 64/4); 256 threads.
template <int K, int NOUT, bool AG, int BN, int TN>
__launch_bounds__(256)
__global__ void sgemm_k(const float* __restrict__ Ain, const float* __restrict__ B, int M) {
    constexpr int BM = 128, BK = 8, TM = 8;
    __shared__ float As[BK][BM];
    __shared__ float Bs[BK][BN];
    const float* A = AG ? (const float*)d_feat : Ain;

    int tid = threadIdx.x;
    int tx = tid & 15, ty = tid >> 4;   // tx: N-dir (16), ty: M-dir (16)
    int row0 = blockIdx.y * BM;
    int col0 = blockIdx.x * BN;
    float acc[TM][TN] = {};

    for (int k0 = 0; k0 < K; k0 += BK) {
        // load A tile: 128 rows x 8 k, float4 per thread
        {
            int r = tid >> 1, kk = (tid & 1) * 4;
            float4 v = make_float4(0.f, 0.f, 0.f, 0.f);
            int gr = row0 + r;
            if (gr < M) v = *reinterpret_cast<const float4*>(&A[(size_t)gr * K + k0 + kk]);
            As[kk + 0][r] = v.x; As[kk + 1][r] = v.y;
            As[kk + 2][r] = v.z; As[kk + 3][r] = v.w;
        }
        // load B tile: 8 rows x BN
        if (BN == 128) {
            int k = tid >> 5, c = (tid & 31) * 4;
            float4 v = *reinterpret_cast<const float4*>(&B[(size_t)(k0 + k) * NOUT + col0 + c]);
            Bs[k][c + 0] = v.x; Bs[k][c + 1] = v.y; Bs[k][c + 2] = v.z; Bs[k][c + 3] = v.w;
        } else {
            int k = tid >> 5, c = (tid & 31) * 2;
            float2 v = *reinterpret_cast<const float2*>(&B[(size_t)(k0 + k) * NOUT + col0 + c]);
            Bs[k][c + 0] = v.x; Bs[k][c + 1] = v.y;
        }
        __syncthreads();
#pragma unroll
        for (int k = 0; k < BK; k++) {
            float a[TM], b[TN];
            float4 a0 = *reinterpret_cast<const float4*>(&As[k][ty * TM]);
            float4 a1 = *reinterpret_cast<const float4*>(&As[k][ty * TM + 4]);
            a[0]=a0.x; a[1]=a0.y; a[2]=a0.z; a[3]=a0.w;
            a[4]=a1.x; a[5]=a1.y; a[6]=a1.z; a[7]=a1.w;
            float4 b0 = *reinterpret_cast<const float4*>(&Bs[k][tx * TN]);
            b[0]=b0.x; b[1]=b0.y; b[2]=b0.z; b[3]=b0.w;
            if (TN == 8) {
                float4 b1 = *reinterpret_cast<const float4*>(&Bs[k][tx * TN + 4]);
                b[4]=b1.x; b[5]=b1.y; b[6]=b1.z; b[7]=b1.w;
            }
#pragma unroll
            for (int i = 0; i < TM; i++)
#pragma unroll
                for (int j = 0; j < TN; j++) acc[i][j] = fmaf(a[i], b[j], acc[i][j]);
        }
        __syncthreads();
    }
#pragma unroll
    for (int i = 0; i < TM; i++) {
        int gr = row0 + ty * TM + i;
        if (gr < M) {
#pragma unroll
            for (int j = 0; j < TN; j += 4) {
                float4 v = make_float4(acc[i][j], acc[i][j+1], acc[i][j+2], acc[i][j+3]);
                *reinterpret_cast<float4*>(&d_h[(size_t)gr * NOUT + col0 + tx * TN + j]) = v;
            }
        }
    }
}

// ========== attention coefficients: asrc/adst[n,H] = <h[n,h,:], a_*[h,:]> ==========
template <int H, int C>
__global__ void attn_coef(const float* __restrict__ a_src, const float* __restrict__ a_dst, int n) {
    int gw = (blockIdx.x * blockDim.x + threadIdx.x) >> 5;
    int lane = threadIdx.x & 31;
    if (gw >= n * H) return;
    int node = gw / H, hd = gw % H;
    const float* hr = d_h + (size_t)node * H * C + hd * C;
    float s1 = 0.f, s2 = 0.f;
#pragma unroll
    for (int c = lane; c < C; c += 32) {
        float v = hr[c];
        s1 += v * a_src[hd * C + c];
        s2 += v * a_dst[hd * C + c];
    }
#pragma unroll
    for (int o = 16; o; o >>= 1) {
        s1 += __shfl_xor_sync(0xffffffffu, s1, o);
        s2 += __shfl_xor_sync(0xffffffffu, s2, o);
    }
    if (!lane) { d_asrc[gw] = s1; d_adst[gw] = s2; }
}

// ========== fused aggregation: warp per destination node ==========
// softmax over incoming edges + weighted sum of h[src] + bias (+ optional ELU)
template <int H, bool DOELU>
__launch_bounds__(256)
__global__ void agg_k(const float* __restrict__ bias, int n) {
    constexpr int C = 64, F = H * C;
    constexpr int RF = F / 32;                  // floats per lane (8 for H=4, 2 for H=1)
    int warp = (blockIdx.x * blockDim.x + threadIdx.x) >> 5;
    int lane = threadIdx.x & 31;
    if (warp >= n) return;
    int dn = warp;
    int off = d_off[dn], deg = d_deg[dn];

    float adst[H];
#pragma unroll
    for (int h = 0; h < H; h++) adst[h] = d_adst[dn * H + h];

    // phase 1a: per-head max over incoming edges
    float mx[H];
#pragma unroll
    for (int h = 0; h < H; h++) mx[h] = -3.402823466e38f;
    for (int j = lane; j < deg; j += 32) {
        int s = d_csr_src[off + j];
#pragma unroll
        for (int h = 0; h < H; h++) {
            float v = d_asrc[s * H + h] + adst[h];
            v = v > 0.f ? v : NEG * v;
            mx[h] = fmaxf(mx[h], v);
        }
    }
#pragma unroll
    for (int h = 0; h < H; h++)
#pragma unroll
        for (int o = 16; o; o >>= 1)
            mx[h] = fmaxf(mx[h], __shfl_xor_sync(0xffffffffu, mx[h], o));

    // phase 1b: per-head sum of exp
    float sm[H];
#pragma unroll
    for (int h = 0; h < H; h++) sm[h] = 0.f;
    for (int j = lane; j < deg; j += 32) {
        int s = d_csr_src[off + j];
#pragma unroll
        for (int h = 0; h < H; h++) {
            float v = d_asrc[s * H + h] + adst[h];
            v = v > 0.f ? v : NEG * v;
            sm[h] += __expf(v - mx[h]);
        }
    }
#pragma unroll
    for (int h = 0; h < H; h++) {
#pragma unroll
        for (int o = 16; o; o >>= 1)
            sm[h] += __shfl_xor_sync(0xffffffffu, sm[h], o);
        sm[h] = 1.f / (sm[h] + EPSV);            // inv denom
    }

    // phase 2: weighted aggregation; lane covers RF contiguous channels
    const int head = (H == 4) ? (lane >> 3) : 0;
    float acc[RF];
#pragma unroll
    for (int k = 0; k < RF; k++) acc[k] = 0.f;

    for (int j = 0; j < deg; j++) {
        int s = d_csr_src[off + j];              // warp-uniform broadcast load
        float v = d_asrc[s * H + head] + adst[head];
        v = v > 0.f ? v : NEG * v;
        float w = __expf(v - mx[head]) * sm[head];
        const float* hs = &d_h[(size_t)s * F + lane * RF];
        if (RF == 8) {
            float4 v0 = *reinterpret_cast<const float4*>(hs);
            float4 v1 = *reinterpret_cast<const float4*>(hs + 4);
            acc[0] = fmaf(w, v0.x, acc[0]); acc[1] = fmaf(w, v0.y, acc[1]);
            acc[2] = fmaf(w, v0.z, acc[2]); acc[3] = fmaf(w, v0.w, acc[3]);
            acc[4] = fmaf(w, v1.x, acc[4]); acc[5] = fmaf(w, v1.y, acc[5]);
            acc[6] = fmaf(w, v1.z, acc[6]); acc[7] = fmaf(w, v1.w, acc[7]);
        } else {
            float2 v0 = *reinterpret_cast<const float2*>(hs);
            acc[0] = fmaf(w, v0.x, acc[0]); acc[1] = fmaf(w, v0.y, acc[1]);
        }
    }

    // bias + optional ELU + single store
    float* outp = &d_feat[(size_t)dn * F + lane * RF];
#pragma unroll
    for (int k = 0; k < RF; k++) {
        float v = acc[k] + bias[lane * RF + k];
        if (DOELU) v = v > 0.f ? v : (__expf(v) - 1.f);
        acc[k] = v;
    }
    if (RF == 8) {
        *reinterpret_cast<float4*>(outp)     = make_float4(acc[0], acc[1], acc[2], acc[3]);
        *reinterpret_cast<float4*>(outp + 4) = make_float4(acc[4], acc[5], acc[6], acc[7]);
    } else {
        *reinterpret_cast<float2*>(outp) = make_float2(acc[0], acc[1]);
    }
}

// ---------------- pooling + head ----------------
__global__ void pool_zero() {
    for (int i = threadIdx.x; i < GG * HIDC; i += blockDim.x) d_pool[i] = 0.f;
    if (threadIdx.x < GG) d_cnt[threadIdx.x] = 0.f;
}

__global__ void pool_add(const int* __restrict__ batch, int n) {
    int i = blockIdx.x * blockDim.x + threadIdx.x;
    if (i >= n * HIDC) return;
    int node = i / HIDC, c = i % HIDC;
    int g = __ldg(&batch[node]);
    atomicAdd(&d_pool[g * HIDC + c], d_feat[(size_t)node * HIDC + c]);
    if (c == 0) atomicAdd(&d_cnt[g], 1.0f);
}

__global__ void head_k(const float* __restrict__ Wc, const float* __restrict__ bc,
                       float* __restrict__ out) {
    int t = blockIdx.x * blockDim.x + threadIdx.x;
    if (t >= GG * OUTC) return;
    int g = t / OUTC, o = t % OUTC;
    float inv = 1.f / fmaxf(d_cnt[g], 1.f);
    float s = 0.f;
#pragma unroll
    for (int c = 0; c < HIDC; c++) s += d_pool[g * HIDC + c] * Wc[c * OUTC + o];
    out[t] = s * inv + bc[o];
}

// ---------------- host orchestration ----------------
extern "C" void kernel_launch(void* const* d_in, const int* in_sizes, int n_in,
                              void* d_out, int out_size) {
    const float* x   = (const float*)d_in[0];
    const int*   ei  = (const int*)d_in[1];
    const int*   bat = (const int*)d_in[2];
    const float* W1 = (const float*)d_in[3],  *as1 = (const float*)d_in[4],
               * ad1 = (const float*)d_in[5], *b1  = (const float*)d_in[6];
    const float* W2 = (const float*)d_in[7],  *as2 = (const float*)d_in[8],
               * ad2 = (const float*)d_in[9], *b2  = (const float*)d_in[10];
    const float* W3 = (const float*)d_in[11], *as3 = (const float*)d_in[12],
               * ad3 = (const float*)d_in[13],*b3  = (const float*)d_in[14];
    const float* Wc = (const float*)d_in[15], *bc  = (const float*)d_in[16];
    float* out = (float*)d_out;

    int n    = in_sizes[0] / INC;
    int E    = in_sizes[1] / 2;
    int Etot = E + n;

    int gemm_rows = (n + 127) / 128;
    int eb   = (Etot + 255) / 256;
    int nb   = (n + 255) / 256;
    int aggb = (n * 32 + 255) / 256;           // warp per node
    int nhb4 = (n * NHEADS * 32 + 255) / 256;

    // ---- CSR build (dst-sorted incoming edges incl. self-loops) ----
    zero_deg<<<nb, 256>>>(n);
    hist_k<<<eb, 256>>>(ei, E, n);
    scan_k<<<1, 1024>>>(n);
    scatter_k<<<eb, 256>>>(ei, E, n);

    // ---- Layer 1 (heads=4, in=128, out=256) ----
    sgemm_k<INC, F1, false, 128, 8><<<dim3(F1 / 128, gemm_rows), 256>>>(x, W1, n);
    attn_coef<NHEADS, HIDC><<<nhb4, 256>>>(as1, ad1, n);
    agg_k<NHEADS, true><<<aggb, 256>>>(b1, n);

    // ---- Layer 2 (heads=4, in=256, out=256) ----
    sgemm_k<F1, F1, true, 128, 8><<<dim3(F1 / 128, gemm_rows), 256>>>(nullptr, W2, n);
    attn_coef<NHEADS, HIDC><<<nhb4, 256>>>(as2, ad2, n);
    agg_k<NHEADS, true><<<aggb, 256>>>(b2, n);

    // ---- Layer 3 (heads=1, in=256, out=64) ----
    sgemm_k<F1, HIDC, true, 64, 4><<<dim3(1, gemm_rows), 256>>>(nullptr, W3, n);
    attn_coef<1, HIDC><<<(n * 32 + 255) / 256, 256>>>(as3, ad3, n);
    agg_k<1, false><<<aggb, 256>>>(b3, n);

    // ---- Global mean pool + linear head ----
    pool_zero<<<1, 256>>>();
    pool_add<<<(n * HIDC + 255) / 256, 256>>>(bat, n);
    head_k<<<(GG * OUTC + 255) / 256, 256>>>(Wc, bc, out);
}

// round 3
// speedup vs baseline: 3.5462x; 1.2986x over previous
#include <cuda_runtime.h>
#include <cstdint>

// ---------------- Problem constants ----------------
#define NMAX    50000
#define EMAX    800000
#define ETOTMAX (EMAX + NMAX)
#define GG      64
#define INC     128
#define HIDC    64
#define NHEADS  4
#define F1      (NHEADS * HIDC)   // 256
#define OUTC    10
#define NEG     0.2f
#define EPSV    1e-16f

// ---------------- Device scratch ----------------
__device__ float d_h[(size_t)NMAX * F1];
__device__ float d_feat[(size_t)NMAX * F1];
__device__ float d_asrc[NMAX * NHEADS];
__device__ float d_adst[NMAX * NHEADS];
__device__ int   d_deg[NMAX];
__device__ int   d_off[NMAX];
__device__ int   d_cur[NMAX];
__device__ int   d_csr_src[ETOTMAX];
__device__ float d_pool[GG * HIDC];
__device__ float d_cnt[GG];

// ================= CSR construction =================
__global__ void zero_deg(int n) {
    int i = blockIdx.x * blockDim.x + threadIdx.x;
    if (i < n) { d_deg[i] = 0; d_cur[i] = 0; }
}

__global__ void hist_k(const int* __restrict__ ei, int E, int n) {
    int e = blockIdx.x * blockDim.x + threadIdx.x;
    int Etot = E + n;
    if (e >= Etot) return;
    int d = (e < E) ? __ldg(&ei[E + e]) : (e - E);
    atomicAdd(&d_deg[d], 1);
}

__global__ void scan_k(int n) {
    const int T = 1024;
    int tid = threadIdx.x;
    int chunk = (n + T - 1) / T;
    int b = tid * chunk;
    int e = min(b + chunk, n);
    int s = 0;
    for (int i = b; i < e; i++) s += d_deg[i];
    __shared__ int ws[32];
    int lane = tid & 31, wid = tid >> 5;
    int v = s;
#pragma unroll
    for (int o = 1; o < 32; o <<= 1) {
        int t = __shfl_up_sync(0xffffffffu, v, o);
        if (lane >= o) v += t;
    }
    if (lane == 31) ws[wid] = v;
    __syncthreads();
    if (wid == 0) {
        int w = (tid < 32) ? ws[tid] : 0;
#pragma unroll
        for (int o = 1; o < 32; o <<= 1) {
            int t = __shfl_up_sync(0xffffffffu, w, o);
            if (lane >= o) w += t;
        }
        if (tid < 32) ws[tid] = w;
    }
    __syncthreads();
    int excl = v - s + (wid ? ws[wid - 1] : 0);
    for (int i = b; i < e; i++) { d_off[i] = excl; excl += d_deg[i]; }
}

__global__ void scatter_k(const int* __restrict__ ei, int E, int n) {
    int e = blockIdx.x * blockDim.x + threadIdx.x;
    int Etot = E + n;
    if (e >= Etot) return;
    int s, d;
    if (e < E) { s = __ldg(&ei[e]); d = __ldg(&ei[E + e]); } else { s = d = e - E; }
    int pos = d_off[d] + atomicAdd(&d_cur[d], 1);
    d_csr_src[pos] = s;
}

// ================= TF32 tensor-core GEMM =================
__device__ __forceinline__ uint32_t cvt_tf32(float x) {
    uint32_t u;
    asm("cvt.rna.tf32.f32 %0, %1;" : "=r"(u) : "f"(x));
    return u;
}

__device__ __forceinline__ void mma_tf32(float c[4], uint32_t a0, uint32_t a1,
                                         uint32_t a2, uint32_t a3,
                                         uint32_t b0, uint32_t b1) {
    asm volatile(
        "mma.sync.aligned.m16n8k8.row.col.f32.tf32.tf32.f32 "
        "{%0,%1,%2,%3}, {%4,%5,%6,%7}, {%8,%9}, {%0,%1,%2,%3};"
        : "+f"(c[0]), "+f"(c[1]), "+f"(c[2]), "+f"(c[3])
        : "r"(a0), "r"(a1), "r"(a2), "r"(a3), "r"(b0), "r"(b1));
}

// d_h[M,NOUT] = A[M,K] @ B[K,NOUT]; CTA tile 128 x BN, BK=32, 8 warps.
template <int K, int NOUT, bool AG, int BN, int WM, int WN>
__launch_bounds__(256, 2)
__global__ void tgemm_k(const float* __restrict__ Ain, const float* __restrict__ B, int M) {
    constexpr int BM = 128, BK = 32;
    constexpr int MT = BM / (WM * 16);     // m16 tiles per warp
    constexpr int NT = BN / (WN * 8);      // n8 tiles per warp
    __shared__ uint32_t As[BK][BM + 8];
    __shared__ uint32_t Bs[BK][BN + 8];
    const float* A = AG ? (const float*)d_feat : Ain;

    int tid = threadIdx.x;
    int wid = tid >> 5, lane = tid & 31;
    int wm = wid % WM, wn = wid / WM;
    int row0 = blockIdx.y * BM;
    int col0 = blockIdx.x * BN;
    int lr = lane >> 2, lc = lane & 3;

    float c[MT][NT][4];
#pragma unroll
    for (int i = 0; i < MT; i++)
#pragma unroll
        for (int j = 0; j < NT; j++)
#pragma unroll
            for (int q = 0; q < 4; q++) c[i][j][q] = 0.f;

    for (int k0 = 0; k0 < K; k0 += BK) {
        // A tile: 128 x 32, 4 float4 per thread, stored k-major
#pragma unroll
        for (int j = 0; j < 4; j++) {
            int idx = tid + j * 256;
            int r = idx >> 3;
            int kk = (idx & 7) * 4;
            float4 v = make_float4(0.f, 0.f, 0.f, 0.f);
            int gr = row0 + r;
            if (gr < M) v = *reinterpret_cast<const float4*>(&A[(size_t)gr * K + k0 + kk]);
            As[kk + 0][r] = cvt_tf32(v.x);
            As[kk + 1][r] = cvt_tf32(v.y);
            As[kk + 2][r] = cvt_tf32(v.z);
            As[kk + 3][r] = cvt_tf32(v.w);
        }
        // B tile: 32 x BN
        constexpr int B4 = BN / 4;                 // float4 per row
        constexpr int BLD = (32 * B4) / 256;       // float4 per thread
#pragma unroll
        for (int j = 0; j < BLD; j++) {
            int idx = tid + j * 256;
            int r = idx / B4;
            int cc = (idx % B4) * 4;
            float4 v = *reinterpret_cast<const float4*>(&B[(size_t)(k0 + r) * NOUT + col0 + cc]);
            Bs[r][cc + 0] = cvt_tf32(v.x);
            Bs[r][cc + 1] = cvt_tf32(v.y);
            Bs[r][cc + 2] = cvt_tf32(v.z);
            Bs[r][cc + 3] = cvt_tf32(v.w);
        }
        __syncthreads();

#pragma unroll
        for (int kk = 0; kk < BK; kk += 8) {
            uint32_t af[MT][4], bf[NT][2];
#pragma unroll
            for (int mt = 0; mt < MT; mt++) {
                int bm = wm * MT * 16 + mt * 16;
                af[mt][0] = As[kk + lc][bm + lr];
                af[mt][1] = As[kk + lc][bm + lr + 8];
                af[mt][2] = As[kk + lc + 4][bm + lr];
                af[mt][3] = As[kk + lc + 4][bm + lr + 8];
            }
#pragma unroll
            for (int nt = 0; nt < NT; nt++) {
                int bn = wn * NT * 8 + nt * 8;
                bf[nt][0] = Bs[kk + lc][bn + lr];
                bf[nt][1] = Bs[kk + lc + 4][bn + lr];
            }
#pragma unroll
            for (int mt = 0; mt < MT; mt++)
#pragma unroll
                for (int nt = 0; nt < NT; nt++)
                    mma_tf32(c[mt][nt], af[mt][0], af[mt][1], af[mt][2], af[mt][3],
                             bf[nt][0], bf[nt][1]);
        }
        __syncthreads();
    }

    // epilogue: c0,c1 at (row, 2*lc), c2,c3 at (row+8, 2*lc)
#pragma unroll
    for (int mt = 0; mt < MT; mt++) {
        int r0 = row0 + wm * MT * 16 + mt * 16 + lr;
#pragma unroll
        for (int nt = 0; nt < NT; nt++) {
            int cc = col0 + wn * NT * 8 + nt * 8 + 2 * lc;
            if (r0 < M)
                *reinterpret_cast<float2*>(&d_h[(size_t)r0 * NOUT + cc]) =
                    make_float2(c[mt][nt][0], c[mt][nt][1]);
            if (r0 + 8 < M)
                *reinterpret_cast<float2*>(&d_h[(size_t)(r0 + 8) * NOUT + cc]) =
                    make_float2(c[mt][nt][2], c[mt][nt][3]);
        }
    }
}

// ========== attention coefficients ==========
template <int H, int C>
__global__ void attn_coef(const float* __restrict__ a_src, const float* __restrict__ a_dst, int n) {
    int gw = (blockIdx.x * blockDim.x + threadIdx.x) >> 5;
    int lane = threadIdx.x & 31;
    if (gw >= n * H) return;
    int node = gw / H, hd = gw % H;
    const float* hr = d_h + (size_t)node * H * C + hd * C;
    float s1 = 0.f, s2 = 0.f;
#pragma unroll
    for (int c = lane; c < C; c += 32) {
        float v = hr[c];
        s1 += v * a_src[hd * C + c];
        s2 += v * a_dst[hd * C + c];
    }
#pragma unroll
    for (int o = 16; o; o >>= 1) {
        s1 += __shfl_xor_sync(0xffffffffu, s1, o);
        s2 += __shfl_xor_sync(0xffffffffu, s2, o);
    }
    if (!lane) { d_asrc[gw] = s1; d_adst[gw] = s2; }
}

// ========== fused aggregation: warp per destination node ==========
template <int H, bool DOELU>
__launch_bounds__(256)
__global__ void agg_k(const float* __restrict__ bias, int n) {
    constexpr int C = 64, F = H * C;
    constexpr int RF = F / 32;
    int warp = (blockIdx.x * blockDim.x + threadIdx.x) >> 5;
    int lane = threadIdx.x & 31;
    if (warp >= n) return;
    int dn = warp;
    int off = d_off[dn], deg = d_deg[dn];

    float adst[H];
#pragma unroll
    for (int h = 0; h < H; h++) adst[h] = d_adst[dn * H + h];

    float mx[H];
#pragma unroll
    for (int h = 0; h < H; h++) mx[h] = -3.402823466e38f;
    for (int j = lane; j < deg; j += 32) {
        int s = d_csr_src[off + j];
#pragma unroll
        for (int h = 0; h < H; h++) {
            float v = d_asrc[s * H + h] + adst[h];
            v = v > 0.f ? v : NEG * v;
            mx[h] = fmaxf(mx[h], v);
        }
    }
#pragma unroll
    for (int h = 0; h < H; h++)
#pragma unroll
        for (int o = 16; o; o >>= 1)
            mx[h] = fmaxf(mx[h], __shfl_xor_sync(0xffffffffu, mx[h], o));

    float sm[H];
#pragma unroll
    for (int h = 0; h < H; h++) sm[h] = 0.f;
    for (int j = lane; j < deg; j += 32) {
        int s = d_csr_src[off + j];
#pragma unroll
        for (int h = 0; h < H; h++) {
            float v = d_asrc[s * H + h] + adst[h];
            v = v > 0.f ? v : NEG * v;
            sm[h] += __expf(v - mx[h]);
        }
    }
#pragma unroll
    for (int h = 0; h < H; h++) {
#pragma unroll
        for (int o = 16; o; o >>= 1)
            sm[h] += __shfl_xor_sync(0xffffffffu, sm[h], o);
        sm[h] = 1.f / (sm[h] + EPSV);
    }

    const int head = (H == 4) ? (lane >> 3) : 0;
    float acc[RF];
#pragma unroll
    for (int k = 0; k < RF; k++) acc[k] = 0.f;

#pragma unroll 2
    for (int j = 0; j < deg; j++) {
        int s = d_csr_src[off + j];
        float v = d_asrc[s * H + head] + adst[head];
        v = v > 0.f ? v : NEG * v;
        float w = __expf(v - mx[head]) * sm[head];
        const float* hs = &d_h[(size_t)s * F + lane * RF];
        if (RF == 8) {
            float4 v0 = *reinterpret_cast<const float4*>(hs);
            float4 v1 = *reinterpret_cast<const float4*>(hs + 4);
            acc[0] = fmaf(w, v0.x, acc[0]); acc[1] = fmaf(w, v0.y, acc[1]);
            acc[2] = fmaf(w, v0.z, acc[2]); acc[3] = fmaf(w, v0.w, acc[3]);
            acc[4] = fmaf(w, v1.x, acc[4]); acc[5] = fmaf(w, v1.y, acc[5]);
            acc[6] = fmaf(w, v1.z, acc[6]); acc[7] = fmaf(w, v1.w, acc[7]);
        } else {
            float2 v0 = *reinterpret_cast<const float2*>(hs);
            acc[0] = fmaf(w, v0.x, acc[0]); acc[1] = fmaf(w, v0.y, acc[1]);
        }
    }

    float* outp = &d_feat[(size_t)dn * F + lane * RF];
#pragma unroll
    for (int k = 0; k < RF; k++) {
        float v = acc[k] + bias[lane * RF + k];
        if (DOELU) v = v > 0.f ? v : (__expf(v) - 1.f);
        acc[k] = v;
    }
    if (RF == 8) {
        *reinterpret_cast<float4*>(outp)     = make_float4(acc[0], acc[1], acc[2], acc[3]);
        *reinterpret_cast<float4*>(outp + 4) = make_float4(acc[4], acc[5], acc[6], acc[7]);
    } else {
        *reinterpret_cast<float2*>(outp) = make_float2(acc[0], acc[1]);
    }
}

// ---------------- pooling + head ----------------
__global__ void pool_zero() {
    for (int i = threadIdx.x; i < GG * HIDC; i += blockDim.x) d_pool[i] = 0.f;
    if (threadIdx.x < GG) d_cnt[threadIdx.x] = 0.f;
}

__global__ void pool_add(const int* __restrict__ batch, int n) {
    int i = blockIdx.x * blockDim.x + threadIdx.x;
    if (i >= n * HIDC) return;
    int node = i / HIDC, c = i % HIDC;
    int g = __ldg(&batch[node]);
    atomicAdd(&d_pool[g * HIDC + c], d_feat[(size_t)node * HIDC + c]);
    if (c == 0) atomicAdd(&d_cnt[g], 1.0f);
}

__global__ void head_k(const float* __restrict__ Wc, const float* __restrict__ bc,
                       float* __restrict__ out) {
    int t = blockIdx.x * blockDim.x + threadIdx.x;
    if (t >= GG * OUTC) return;
    int g = t / OUTC, o = t % OUTC;
    float inv = 1.f / fmaxf(d_cnt[g], 1.f);
    float s = 0.f;
#pragma unroll
    for (int c = 0; c < HIDC; c++) s += d_pool[g * HIDC + c] * Wc[c * OUTC + o];
    out[t] = s * inv + bc[o];
}

// ---------------- host orchestration ----------------
extern "C" void kernel_launch(void* const* d_in, const int* in_sizes, int n_in,
                              void* d_out, int out_size) {
    const float* x   = (const float*)d_in[0];
    const int*   ei  = (const int*)d_in[1];
    const int*   bat = (const int*)d_in[2];
    const float* W1 = (const float*)d_in[3],  *as1 = (const float*)d_in[4],
               * ad1 = (const float*)d_in[5], *b1  = (const float*)d_in[6];
    const float* W2 = (const float*)d_in[7],  *as2 = (const float*)d_in[8],
               * ad2 = (const float*)d_in[9], *b2  = (const float*)d_in[10];
    const float* W3 = (const float*)d_in[11], *as3 = (const float*)d_in[12],
               * ad3 = (const float*)d_in[13],*b3  = (const float*)d_in[14];
    const float* Wc = (const float*)d_in[15], *bc  = (const float*)d_in[16];
    float* out = (float*)d_out;

    int n    = in_sizes[0] / INC;
    int E    = in_sizes[1] / 2;
    int Etot = E + n;

    int gemm_rows = (n + 127) / 128;
    int eb   = (Etot + 255) / 256;
    int nb   = (n + 255) / 256;
    int aggb = (n * 32 + 255) / 256;
    int nhb4 = (n * NHEADS * 32 + 255) / 256;

    // ---- CSR build ----
    zero_deg<<<nb, 256>>>(n);
    hist_k<<<eb, 256>>>(ei, E, n);
    scan_k<<<1, 1024>>>(n);
    scatter_k<<<eb, 256>>>(ei, E, n);

    // ---- Layer 1 (heads=4, in=128, out=256) ----
    tgemm_k<INC, F1, false, 128, 2, 4><<<dim3(F1 / 128, gemm_rows), 256>>>(x, W1, n);
    attn_coef<NHEADS, HIDC><<<nhb4, 256>>>(as1, ad1, n);
    agg_k<NHEADS, true><<<aggb, 256>>>(b1, n);

    // ---- Layer 2 (heads=4, in=256, out=256) ----
    tgemm_k<F1, F1, true, 128, 2, 4><<<dim3(F1 / 128, gemm_rows), 256>>>(nullptr, W2, n);
    attn_coef<NHEADS, HIDC><<<nhb4, 256>>>(as2, ad2, n);
    agg_k<NHEADS, true><<<aggb, 256>>>(b2, n);

    // ---- Layer 3 (heads=1, in=256, out=64) ----
    tgemm_k<F1, HIDC, true, 64, 4, 2><<<dim3(1, gemm_rows), 256>>>(nullptr, W3, n);
    attn_coef<1, HIDC><<<(n * 32 + 255) / 256, 256>>>(as3, ad3, n);
    agg_k<1, false><<<aggb, 256>>>(b3, n);

    // ---- Global mean pool + linear head ----
    pool_zero<<<1, 256>>>();
    pool_add<<<(n * HIDC + 255) / 256, 256>>>(bat, n);
    head_k<<<(GG * OUTC + 255) / 256, 256>>>(Wc, bc, out);
}